// round 2
// baseline (speedup 1.0000x reference)
#include <cuda_runtime.h>

// out[b, n, :] = (cnn[b] @ Wkv[:, 768:1536]) @ Wp + bp      (independent of n!)
// image_patches and Wq are dead (softmax over kv_len=1 -> attn == 1).

#define B_SZ   64
#define N_SEQ  576
#define C_DIM  768
#define K1     2048
#define LDKV   1536

#define TN     128            // block tile n-width
#define NT     (C_DIM / TN)   // 6
#define KS1    64             // split-K for GEMM1 -> 384 blocks
#define KC1    (K1 / KS1)     // 32
#define KS2    24             // split-K for GEMM2 -> 144 blocks (one wave)
#define KC2    (C_DIM / KS2)  // 32

// Scratch (__device__ globals; allocations are forbidden)
__device__ float g_p1[KS1 * B_SZ * C_DIM];   // GEMM1 partials (12.6 MB)
__device__ float g_v [B_SZ * C_DIM];         // v = cnn @ Wkv_v
__device__ float g_p2[KS2 * B_SZ * C_DIM];   // GEMM2 partials (4.7 MB)
__device__ float g_y [B_SZ * C_DIM];         // y = v @ Wp + bp

// ---- packed f32x2 helpers (FFMA2: 2 FMA per fma-pipe slot; PTX-only) ------
__device__ __forceinline__ unsigned long long pack2(float x) {
    unsigned long long r;
    unsigned int xi = __float_as_uint(x);
    asm("mov.b64 %0, {%1, %1};" : "=l"(r) : "r"(xi));
    return r;
}
__device__ __forceinline__ void fma2(unsigned long long& d,
                                     unsigned long long a, unsigned long long b) {
    asm("fma.rn.f32x2 %0, %1, %2, %0;" : "+l"(d) : "l"(a), "l"(b));
}
__device__ __forceinline__ float2 u2f(unsigned long long u) {
    float2 f;
    asm("mov.b64 {%0, %1}, %2;" : "=f"(f.x), "=f"(f.y) : "l"(u));
    return f;
}

// ---------------------------------------------------------------------------
// Tile GEMM: P[64 x 128] = A[64 x KCHUNK] * B[KCHUNK x 128]
// 256 threads, each owns a 4(m) x 8(n) micro-tile.
// Inner k-step per thread: 3x LDS.128 + 4 packs + 16 FFMA2 (= 32 FMA).
// ---------------------------------------------------------------------------
template<int KCHUNK>
__device__ __forceinline__ void gemm_tile(
    const float* __restrict__ A, int lda,
    const float* __restrict__ Bm, int ldb,
    float* __restrict__ Pout)
{
    __shared__ float As[16][68];    // [k][m], 272B rows (16B aligned), transposed A
    __shared__ float Bs[16][TN];    // [k][n]

    const int tid = threadIdx.x;
    const int tx = tid & 15;        // n group: 8 columns
    const int ty = tid >> 4;        // m group: 4 rows

    unsigned long long acc[4][4];   // [m][n-pair], pairs are (n,n+1)
    #pragma unroll
    for (int i = 0; i < 4; ++i)
        #pragma unroll
        for (int j = 0; j < 4; ++j) acc[i][j] = 0ull;

    for (int kt = 0; kt < KCHUNK; kt += 16) {
        // A tile 64x16, coalesced float4 loads, transposed store
        {
            int m  = tid >> 2;              // 0..63
            int kq = (tid & 3) * 4;         // 0,4,8,12
            float4 a = *(const float4*)&A[m * lda + kt + kq];
            As[kq + 0][m] = a.x;
            As[kq + 1][m] = a.y;
            As[kq + 2][m] = a.z;
            As[kq + 3][m] = a.w;
        }
        // B tile 16x128, two float4 per thread
        {
            int k  = tid >> 4;              // 0..15
            int n8 = (tid & 15) * 8;        // 0..120
            const float* src = &Bm[(kt + k) * ldb + n8];
            *(float4*)&Bs[k][n8]     = *(const float4*)&src[0];
            *(float4*)&Bs[k][n8 + 4] = *(const float4*)&src[4];
        }
        __syncthreads();

        #pragma unroll
        for (int k = 0; k < 16; ++k) {
            float4 a = *(const float4*)&As[k][ty * 4];
            ulonglong2 b0 = *(const ulonglong2*)&Bs[k][tx * 8];      // (n0,n1),(n2,n3)
            ulonglong2 b1 = *(const ulonglong2*)&Bs[k][tx * 8 + 4];  // (n4,n5),(n6,n7)
            unsigned long long a0 = pack2(a.x);
            unsigned long long a1 = pack2(a.y);
            unsigned long long a2 = pack2(a.z);
            unsigned long long a3 = pack2(a.w);
            fma2(acc[0][0], a0, b0.x); fma2(acc[0][1], a0, b0.y);
            fma2(acc[0][2], a0, b1.x); fma2(acc[0][3], a0, b1.y);
            fma2(acc[1][0], a1, b0.x); fma2(acc[1][1], a1, b0.y);
            fma2(acc[1][2], a1, b1.x); fma2(acc[1][3], a1, b1.y);
            fma2(acc[2][0], a2, b0.x); fma2(acc[2][1], a2, b0.y);
            fma2(acc[2][2], a2, b1.x); fma2(acc[2][3], a2, b1.y);
            fma2(acc[3][0], a3, b0.x); fma2(acc[3][1], a3, b0.y);
            fma2(acc[3][2], a3, b1.x); fma2(acc[3][3], a3, b1.y);
        }
        __syncthreads();
    }

    #pragma unroll
    for (int i = 0; i < 4; ++i) {
        float2 f0 = u2f(acc[i][0]);
        float2 f1 = u2f(acc[i][1]);
        float2 f2 = u2f(acc[i][2]);
        float2 f3 = u2f(acc[i][3]);
        float* row = Pout + (ty * 4 + i) * C_DIM + tx * 8;
        *(float4*)(row)     = make_float4(f0.x, f0.y, f1.x, f1.y);
        *(float4*)(row + 4) = make_float4(f2.x, f2.y, f3.x, f3.y);
    }
}

// GEMM1: partials of cnn[64,2048] @ Wkv[:, 768:1536]
__global__ void __launch_bounds__(256, 3)
gemm1_kernel(const float* __restrict__ cnn, const float* __restrict__ Wkv)
{
    int ntile = blockIdx.x % NT;
    int split = blockIdx.x / NT;
    int n0 = ntile * TN;
    gemm_tile<KC1>(cnn + split * KC1, K1,
                   Wkv + (size_t)(split * KC1) * LDKV + C_DIM + n0, LDKV,
                   g_p1 + split * (B_SZ * C_DIM) + n0);
}

// Reduce GEMM1 partials -> g_v
__global__ void __launch_bounds__(256)
reduce1_kernel()
{
    int idx = blockIdx.x * 256 + threadIdx.x;   // float4 index, 12288 total
    const float4* p = (const float4*)g_p1;
    float4 s = make_float4(0.f, 0.f, 0.f, 0.f);
    #pragma unroll
    for (int sp = 0; sp < KS1; ++sp) {
        float4 t = p[sp * (B_SZ * C_DIM / 4) + idx];
        s.x += t.x; s.y += t.y; s.z += t.z; s.w += t.w;
    }
    ((float4*)g_v)[idx] = s;
}

// GEMM2: partials of v[64,768] @ Wp[768,768]
__global__ void __launch_bounds__(256, 3)
gemm2_kernel(const float* __restrict__ Wp)
{
    int ntile = blockIdx.x % NT;
    int split = blockIdx.x / NT;
    int n0 = ntile * TN;
    gemm_tile<KC2>(g_v + split * KC2, C_DIM,
                   Wp + (size_t)(split * KC2) * C_DIM + n0, C_DIM,
                   g_p2 + split * (B_SZ * C_DIM) + n0);
}

// Reduce GEMM2 partials + bias -> g_y
__global__ void __launch_bounds__(256)
reduce2_kernel(const float* __restrict__ bp)
{
    int idx = blockIdx.x * 256 + threadIdx.x;   // float4 index, 12288 total
    const float4* p = (const float4*)g_p2;
    float4 s = ((const float4*)bp)[idx % (C_DIM / 4)];
    #pragma unroll
    for (int sp = 0; sp < KS2; ++sp) {
        float4 t = p[sp * (B_SZ * C_DIM / 4) + idx];
        s.x += t.x; s.y += t.y; s.z += t.z; s.w += t.w;
    }
    ((float4*)g_y)[idx] = s;
}

// Broadcast y over N=576. Pure streaming stores; 4608 blocks for parallelism.
__global__ void __launch_bounds__(192)
bcast_kernel(float* __restrict__ out)
{
    int b  = blockIdx.x / 72;          // batch
    int nc = blockIdx.x % 72;          // 8-row chunk
    int c4 = threadIdx.x;              // float4 column 0..191

    float4 y = ((const float4*)g_y)[b * (C_DIM / 4) + c4];
    float4* o = (float4*)out + (size_t)(b * N_SEQ + nc * 8) * (C_DIM / 4) + c4;
    #pragma unroll
    for (int n = 0; n < 8; ++n) {
        *o = y;
        o += C_DIM / 4;
    }
}

extern "C" void kernel_launch(void* const* d_in, const int* in_sizes, int n_in,
                              void* d_out, int out_size)
{
    (void)in_sizes; (void)n_in; (void)out_size;
    // Inputs: image_patches, cnn_feature_vector, Wq, Wkv, Wp, bp
    const float* cnn = (const float*)d_in[1];
    const float* Wkv = (const float*)d_in[3];
    const float* Wp  = (const float*)d_in[4];
    const float* bp  = (const float*)d_in[5];
    float* out = (float*)d_out;

    gemm1_kernel<<<NT * KS1, 256>>>(cnn, Wkv);
    reduce1_kernel<<<(B_SZ * C_DIM / 4) / 256, 256>>>();
    gemm2_kernel<<<NT * KS2, 256>>>(Wp);
    reduce2_kernel<<<(B_SZ * C_DIM / 4) / 256, 256>>>(bp);
    bcast_kernel<<<B_SZ * 72, 192>>>(out);
}

// round 3
// speedup vs baseline: 1.0390x; 1.0390x over previous
#include <cuda_runtime.h>
#include <cstdint>

// out[b, n, :] = (cnn[b] @ Wkv[:, 768:1536]) @ Wp + bp   (independent of n)
// image_patches and Wq are dead: softmax over kv_len=1 -> attn == 1.

#define B_SZ   64
#define N_SEQ  576
#define C_DIM  768
#define K1     2048
#define LDKV   1536

// GEMM1: tile 64x128, NT1=6 n-tiles, KS1=32 splits (KC1=64) -> 192 blocks
#define NT1    6
#define KS1    32
#define KC1    64
// GEMM2: tile 64x64, NT2=12 n-tiles, KS2=12 splits (KC2=64) -> 144 blocks
#define NT2    12
#define KS2    12
#define KC2    64

// Scratch (allocations forbidden -> __device__ globals)
__device__ float g_p1[KS1 * B_SZ * C_DIM];   // GEMM1 split-K partials (6.3 MB)
__device__ float g_v [B_SZ * C_DIM];         // v = cnn @ Wkv_v (overwritten each call)
__device__ float g_y [B_SZ * C_DIM];         // y; re-initialized to bias by gemm1 each call

// ---- packed f32x2 helpers (FFMA2) -----------------------------------------
__device__ __forceinline__ unsigned long long pack2(float x) {
    unsigned long long r;
    unsigned int xi = __float_as_uint(x);
    asm("mov.b64 %0, {%1, %1};" : "=l"(r) : "r"(xi));
    return r;
}
__device__ __forceinline__ void fma2(unsigned long long& d,
                                     unsigned long long a, unsigned long long b) {
    asm("fma.rn.f32x2 %0, %1, %2, %0;" : "+l"(d) : "l"(a), "l"(b));
}
__device__ __forceinline__ float2 u2f(unsigned long long u) {
    float2 f;
    asm("mov.b64 {%0, %1}, %2;" : "=f"(f.x), "=f"(f.y) : "l"(u));
    return f;
}
__device__ __forceinline__ void redg_add(float* p, float v) {
    asm volatile("red.global.add.f32 [%0], %1;" :: "l"(p), "f"(v) : "memory");
}
__device__ __forceinline__ uint32_t smem_u32(const void* p) {
    uint32_t a;
    asm("{ .reg .u64 t; cvta.to.shared.u64 t, %1; cvt.u32.u64 %0, t; }" : "=r"(a) : "l"(p));
    return a;
}

// ---------------------------------------------------------------------------
// GEMM1: partials of cnn[64,2048] @ Wkv[:,768:1536]. Tile 64x128.
// Prologue: re-initialize g_y with the bias (consumed by gemm2's REDG adds).
// ---------------------------------------------------------------------------
__global__ void __launch_bounds__(256, 3)
gemm1_kernel(const float* __restrict__ cnn, const float* __restrict__ Wkv,
             const float* __restrict__ bp)
{
    const int tid = threadIdx.x;

    // g_y[m][c] = bp[c]; 192 blocks x 64 float4 = 12288 float4 covers all of g_y
    if (tid < 64) {
        int idx = blockIdx.x * 64 + tid;                  // 0..12287
        ((float4*)g_y)[idx] = ((const float4*)bp)[idx % (C_DIM / 4)];
    }

    __shared__ float As[16][68];
    __shared__ float Bs[16][128];

    int ntile = blockIdx.x % NT1;
    int split = blockIdx.x / NT1;
    int n0 = ntile * 128;
    const float* A  = cnn + split * KC1;                                 // lda = K1
    const float* Bm = Wkv + (size_t)(split * KC1) * LDKV + C_DIM + n0;   // ldb = LDKV

    const int tx = tid & 15;   // 8 cols
    const int ty = tid >> 4;   // 4 rows

    unsigned long long acc[4][4];
    #pragma unroll
    for (int i = 0; i < 4; ++i)
        #pragma unroll
        for (int j = 0; j < 4; ++j) acc[i][j] = 0ull;

    for (int kt = 0; kt < KC1; kt += 16) {
        {
            int m  = tid >> 2;
            int kq = (tid & 3) * 4;
            float4 a = *(const float4*)&A[m * K1 + kt + kq];
            As[kq + 0][m] = a.x; As[kq + 1][m] = a.y;
            As[kq + 2][m] = a.z; As[kq + 3][m] = a.w;
        }
        {
            int k  = tid >> 4;
            int n8 = (tid & 15) * 8;
            const float* src = &Bm[(kt + k) * LDKV + n8];
            *(float4*)&Bs[k][n8]     = *(const float4*)&src[0];
            *(float4*)&Bs[k][n8 + 4] = *(const float4*)&src[4];
        }
        __syncthreads();

        #pragma unroll
        for (int k = 0; k < 16; ++k) {
            float4 a = *(const float4*)&As[k][ty * 4];
            ulonglong2 b0 = *(const ulonglong2*)&Bs[k][tx * 8];
            ulonglong2 b1 = *(const ulonglong2*)&Bs[k][tx * 8 + 4];
            unsigned long long a0 = pack2(a.x), a1 = pack2(a.y);
            unsigned long long a2 = pack2(a.z), a3 = pack2(a.w);
            fma2(acc[0][0], a0, b0.x); fma2(acc[0][1], a0, b0.y);
            fma2(acc[0][2], a0, b1.x); fma2(acc[0][3], a0, b1.y);
            fma2(acc[1][0], a1, b0.x); fma2(acc[1][1], a1, b0.y);
            fma2(acc[1][2], a1, b1.x); fma2(acc[1][3], a1, b1.y);
            fma2(acc[2][0], a2, b0.x); fma2(acc[2][1], a2, b0.y);
            fma2(acc[2][2], a2, b1.x); fma2(acc[2][3], a2, b1.y);
            fma2(acc[3][0], a3, b0.x); fma2(acc[3][1], a3, b0.y);
            fma2(acc[3][2], a3, b1.x); fma2(acc[3][3], a3, b1.y);
        }
        __syncthreads();
    }

    float* Pout = g_p1 + split * (B_SZ * C_DIM) + n0;
    #pragma unroll
    for (int i = 0; i < 4; ++i) {
        float2 f0 = u2f(acc[i][0]), f1 = u2f(acc[i][1]);
        float2 f2 = u2f(acc[i][2]), f3 = u2f(acc[i][3]);
        float* row = Pout + (ty * 4 + i) * C_DIM + tx * 8;
        *(float4*)(row)     = make_float4(f0.x, f0.y, f1.x, f1.y);
        *(float4*)(row + 4) = make_float4(f2.x, f2.y, f3.x, f3.y);
    }
}

// Reduce GEMM1 partials -> g_v.  grid 192 x 64 threads, 1 float4 per thread.
__global__ void __launch_bounds__(64)
reduce1_kernel()
{
    int idx = blockIdx.x * 64 + threadIdx.x;             // 0..12287
    const float4* p = (const float4*)g_p1;
    float4 s = make_float4(0.f, 0.f, 0.f, 0.f);
    #pragma unroll
    for (int sp = 0; sp < KS1; ++sp) {
        float4 t = p[sp * (B_SZ * C_DIM / 4) + idx];
        s.x += t.x; s.y += t.y; s.z += t.z; s.w += t.w;
    }
    ((float4*)g_v)[idx] = s;
}

// ---------------------------------------------------------------------------
// GEMM2: v[64,768] @ Wp[768,768], tile 64x64, epilogue = red.global.add into g_y
// (g_y was pre-loaded with the bias by gemm1's prologue).
// ---------------------------------------------------------------------------
__global__ void __launch_bounds__(256, 3)
gemm2_kernel(const float* __restrict__ Wp)
{
    __shared__ float As[16][68];
    __shared__ float Bs[16][64];

    const int tid = threadIdx.x;
    int ntile = blockIdx.x % NT2;
    int split = blockIdx.x / NT2;
    int n0 = ntile * 64;
    const float* A  = g_v + split * KC2;                           // lda = C_DIM
    const float* Bm = Wp + (size_t)(split * KC2) * C_DIM + n0;     // ldb = C_DIM

    const int tx = tid & 15;   // 4 cols
    const int ty = tid >> 4;   // 4 rows

    unsigned long long acc[4][2];
    #pragma unroll
    for (int i = 0; i < 4; ++i) { acc[i][0] = 0ull; acc[i][1] = 0ull; }

    for (int kt = 0; kt < KC2; kt += 16) {
        {
            int m  = tid >> 2;
            int kq = (tid & 3) * 4;
            float4 a = *(const float4*)&A[m * C_DIM + kt + kq];
            As[kq + 0][m] = a.x; As[kq + 1][m] = a.y;
            As[kq + 2][m] = a.z; As[kq + 3][m] = a.w;
        }
        {
            int k  = tid >> 4;
            int n4 = (tid & 15) * 4;
            *(float4*)&Bs[k][n4] = *(const float4*)&Bm[(kt + k) * C_DIM + n4];
        }
        __syncthreads();

        #pragma unroll
        for (int k = 0; k < 16; ++k) {
            float4 a = *(const float4*)&As[k][ty * 4];
            ulonglong2 b = *(const ulonglong2*)&Bs[k][tx * 4];
            unsigned long long a0 = pack2(a.x), a1 = pack2(a.y);
            unsigned long long a2 = pack2(a.z), a3 = pack2(a.w);
            fma2(acc[0][0], a0, b.x); fma2(acc[0][1], a0, b.y);
            fma2(acc[1][0], a1, b.x); fma2(acc[1][1], a1, b.y);
            fma2(acc[2][0], a2, b.x); fma2(acc[2][1], a2, b.y);
            fma2(acc[3][0], a3, b.x); fma2(acc[3][1], a3, b.y);
        }
        __syncthreads();
    }

    #pragma unroll
    for (int i = 0; i < 4; ++i) {
        float2 f0 = u2f(acc[i][0]);
        float2 f1 = u2f(acc[i][1]);
        float* p = g_y + (ty * 4 + i) * C_DIM + n0 + tx * 4;
        redg_add(p + 0, f0.x);
        redg_add(p + 1, f0.y);
        redg_add(p + 2, f1.x);
        redg_add(p + 3, f1.y);
    }
}

// ---------------------------------------------------------------------------
// Broadcast y over N=576 via TMA bulk stores (smem -> gmem), 64 rows per block.
// grid = 64 batches x 9 chunks = 576 blocks, 192 threads.
// ---------------------------------------------------------------------------
__global__ void __launch_bounds__(192)
bcast_kernel(float* __restrict__ out)
{
    __shared__ __align__(16) float ys[C_DIM];

    int b     = blockIdx.x / 9;
    int chunk = blockIdx.x % 9;
    int c4    = threadIdx.x;                 // 0..191

    ((float4*)ys)[c4] = ((const float4*)g_y)[b * (C_DIM / 4) + c4];
    __syncthreads();
    asm volatile("fence.proxy.async.shared::cta;" ::: "memory");

    uint32_t s = smem_u32(ys);
    if (threadIdx.x < 64) {
        float* g = out + (size_t)(b * N_SEQ + chunk * 64 + threadIdx.x) * C_DIM;
        asm volatile("cp.async.bulk.global.shared::cta.bulk_group [%0], [%1], %2;"
                     :: "l"(g), "r"(s), "n"(C_DIM * 4) : "memory");
        asm volatile("cp.async.bulk.commit_group;" ::: "memory");
        asm volatile("cp.async.bulk.wait_group 0;" ::: "memory");
    }
}

extern "C" void kernel_launch(void* const* d_in, const int* in_sizes, int n_in,
                              void* d_out, int out_size)
{
    (void)in_sizes; (void)n_in; (void)out_size;
    // Inputs: image_patches, cnn_feature_vector, Wq, Wkv, Wp, bp
    const float* cnn = (const float*)d_in[1];
    const float* Wkv = (const float*)d_in[3];
    const float* Wp  = (const float*)d_in[4];
    const float* bp  = (const float*)d_in[5];
    float* out = (float*)d_out;

    gemm1_kernel<<<NT1 * KS1, 256>>>(cnn, Wkv, bp);   // 192 blocks
    reduce1_kernel<<<192, 64>>>();                    // 192 blocks
    gemm2_kernel<<<NT2 * KS2, 256>>>(Wp);             // 144 blocks
    bcast_kernel<<<B_SZ * 9, 192>>>(out);             // 576 blocks
}